// round 6
// baseline (speedup 1.0000x reference)
#include <cuda_runtime.h>
#include <cuda_bf16.h>
#include <stdint.h>

// Problem constants (fixed by setup_inputs)
#define NNODE 1024
#define SD 8
#define DD 64
#define OUTDIM 8192
#define EPSV 1e-4f
#define NS_ITERS 18
#define PMAX 32768

// Static device scratch (no allocation allowed).
// g_tab is NEVER initialized: entries are validated on read against E
// (p valid iff 0<=p<P && E[2p]==i && E[2p+1]==j), so stale/garbage values
// are harmless and the result is deterministic across graph replays.
__device__ float g_diag[NNODE * DD];        // segment-sum of F^T F per source node
__device__ float g_dis[NNODE * DD];         // D^{-1/2} per node
__device__ float g_db[NNODE * DD];          // diagonal output blocks Dis*diag*Dis
__device__ float g_eb[PMAX * DD];           // compact off-diagonal edge blocks
__device__ int   g_tab[NNODE * NNODE];      // (i,j) -> edge index (validated)

// ---------------------------------------------------------------------------
// K1: scatter edge indices into the lookup table; also zero g_diag.
__global__ void k_scatter(const int* __restrict__ E, int P) {
    int idx = blockIdx.x * blockDim.x + threadIdx.x;
    if (idx < P) {
        int i = E[2 * idx], j = E[2 * idx + 1];
        g_tab[i * NNODE + j] = idx;
    }
    // zero the diag accumulator (NNODE*DD = 65536 floats)
    int stride = gridDim.x * blockDim.x;
    for (int q = idx; q < NNODE * DD; q += stride) g_diag[q] = 0.f;
}

// K2: FtF[p] = R_p^T R_p accumulated into g_diag[src]. 16 edges per 256-thread
// CTA; one burst float4 shared load (4KB) for high MLP, then 4 elems/thread.
__global__ void k_ftf(const float* __restrict__ R, const int* __restrict__ E, int P) {
    __shared__ float sR[16 * DD];
    __shared__ int ssrc[16];
    int t = threadIdx.x;
    int e0 = blockIdx.x * 16;
    int nE = P - e0; if (nE > 16) nE = 16;
    const float4* Rv = (const float4*)(R + (long)e0 * DD);
    if (t < nE * 16) ((float4*)sR)[t] = Rv[t];
    if (t < nE) ssrc[t] = E[2 * (e0 + t)];
    __syncthreads();
    int grp = t >> 6, el = t & 63;
    int i = el >> 3, j = el & 7;
#pragma unroll
    for (int q = 0; q < 4; q++) {
        int le = grp * 4 + q;
        if (le < nE) {
            const float* r = &sR[le * DD];
            float v = 0.f;
#pragma unroll
            for (int k = 0; k < 8; k++) v += r[k * 8 + i] * r[k * 8 + j];
            atomicAdd(&g_diag[ssrc[le] * DD + el], v);
        }
    }
}

// K3: warp-per-node Newton-Schulz D^{-1/2}; also emit diagonal block
// Dis * diag_raw * Dis into g_db. 8 nodes (warps) per 256-thread CTA.
__global__ void k_node() {
    __shared__ float sD[8][DD], sY[8][DD], sZ[8][DD], sT[8][DD];
    int t = threadIdx.x;
    int w = t >> 5, lane = t & 31;
    int node = blockIdx.x * 8 + w;
    int e0 = lane, e1 = lane + 32;
    int i0 = e0 >> 3, j0 = e0 & 7, i1 = e1 >> 3, j1 = e1 & 7;

    sD[w][e0] = g_diag[node * DD + e0];
    sD[w][e1] = g_diag[node * DD + e1];
    __syncwarp();

    float c = 8.f * EPSV;
#pragma unroll
    for (int k = 0; k < 8; k++) c += sD[w][k * 9];
    float invc = 1.f / c;

    float y0 = (0.5f * (sD[w][e0] + sD[w][j0 * 8 + i0]) + ((i0 == j0) ? EPSV : 0.f)) * invc;
    float y1 = (0.5f * (sD[w][e1] + sD[w][j1 * 8 + i1]) + ((i1 == j1) ? EPSV : 0.f)) * invc;
    __syncwarp();
    sY[w][e0] = y0; sY[w][e1] = y1;
    sZ[w][e0] = (i0 == j0) ? 1.f : 0.f;
    sZ[w][e1] = (i1 == j1) ? 1.f : 0.f;
    __syncwarp();

    for (int it = 0; it < NS_ITERS; it++) {
        float t0 = 0.f, t1 = 0.f;
#pragma unroll
        for (int k = 0; k < 8; k++) {
            t0 += sZ[w][i0 * 8 + k] * sY[w][k * 8 + j0];
            t1 += sZ[w][i1 * 8 + k] * sY[w][k * 8 + j1];
        }
        __syncwarp();
        sT[w][e0] = t0; sT[w][e1] = t1;
        __syncwarp();
        float ny0 = 0.f, ny1 = 0.f, nz0 = 0.f, nz1 = 0.f;
#pragma unroll
        for (int k = 0; k < 8; k++) {
            ny0 += sY[w][i0 * 8 + k] * sT[w][k * 8 + j0];
            ny1 += sY[w][i1 * 8 + k] * sT[w][k * 8 + j1];
            nz0 += sT[w][i0 * 8 + k] * sZ[w][k * 8 + j0];
            nz1 += sT[w][i1 * 8 + k] * sZ[w][k * 8 + j1];
        }
        ny0 = 1.5f * sY[w][e0] - 0.5f * ny0;
        ny1 = 1.5f * sY[w][e1] - 0.5f * ny1;
        nz0 = 1.5f * sZ[w][e0] - 0.5f * nz0;
        nz1 = 1.5f * sZ[w][e1] - 0.5f * nz1;
        __syncwarp();
        sY[w][e0] = ny0; sY[w][e1] = ny1;
        sZ[w][e0] = nz0; sZ[w][e1] = nz1;
        __syncwarp();
    }

    float rs = rsqrtf(c);
    float d0 = sZ[w][e0] * rs, d1 = sZ[w][e1] * rs;
    __syncwarp();
    sT[w][e0] = d0; sT[w][e1] = d1;
    __syncwarp();
    d0 = 0.5f * (sT[w][e0] + sT[w][j0 * 8 + i0]);
    d1 = 0.5f * (sT[w][e1] + sT[w][j1 * 8 + i1]);
    g_dis[node * DD + e0] = d0;
    g_dis[node * DD + e1] = d1;
    __syncwarp();
    sZ[w][e0] = d0; sZ[w][e1] = d1;   // Dis
    __syncwarp();
    float b0 = 0.f, b1 = 0.f;
#pragma unroll
    for (int k = 0; k < 8; k++) {
        b0 += sZ[w][i0 * 8 + k] * sD[w][k * 8 + j0];
        b1 += sZ[w][i1 * 8 + k] * sD[w][k * 8 + j1];
    }
    __syncwarp();
    sT[w][e0] = b0; sT[w][e1] = b1;
    __syncwarp();
    float c0 = 0.f, c1 = 0.f;
#pragma unroll
    for (int k = 0; k < 8; k++) {
        c0 += sT[w][i0 * 8 + k] * sZ[w][k * 8 + j0];
        c1 += sT[w][i1 * 8 + k] * sZ[w][k * 8 + j1];
    }
    g_db[node * DD + e0] = c0;
    g_db[node * DD + e1] = c1;
}

// K4: per-edge off-diagonal block into COMPACT g_eb[p]:
//   M = -sign(L1[i,j]) * F_ji^T * F_ij ;  eb = Dis_i * M * Dis_j
// Reverse-edge lookup is validated against E (table is uninitialized).
__global__ void k_edge(const float* __restrict__ R, const int* __restrict__ E,
                       const float* __restrict__ L1, int P) {
    __shared__ float sA[4][DD], sB[4][DD], sDi[4][DD], sDj[4][DD];
    __shared__ float ssgn[4];
    __shared__ int srev[4];
    int t = threadIdx.x;
    int ln = t >> 6, el = t & 63;
    int i = el >> 3, j = el & 7;
    int p = blockIdx.x * 4 + ln;
    bool active = (p < P);

    int ni = 0, nj = 0;
    if (active) {
        ni = __ldg(&E[2 * p]);
        nj = __ldg(&E[2 * p + 1]);
        if (el == 0) {
            int rev = g_tab[nj * NNODE + ni];
            // validate (uninitialized table)
            if (rev < 0 || rev >= P || __ldg(&E[2 * rev]) != nj || __ldg(&E[2 * rev + 1]) != ni)
                rev = -1;
            srev[ln] = rev;
            float x = __ldg(&L1[(long)ni * NNODE + nj]);
            ssgn[ln] = (x > 0.f) ? -1.f : ((x < 0.f) ? 1.f : 0.f);
        }
    }
    __syncthreads();

    float m = 0.f;
    if (active) {
        int rev = srev[ln];
        sA[ln][el] = __ldg(&R[(long)p * DD + el]);
        sB[ln][el] = (rev >= 0) ? __ldg(&R[(long)rev * DD + el]) : 0.f;
        sDi[ln][el] = g_dis[ni * DD + el];
        sDj[ln][el] = g_dis[nj * DD + el];
    }
    __syncthreads();
    if (active) {
        float msgn = ssgn[ln];
#pragma unroll
        for (int k = 0; k < 8; k++) m += sB[ln][k * 8 + i] * sA[ln][k * 8 + j];
        m *= msgn;
    }
    __syncthreads();
    if (active) sA[ln][el] = m;
    __syncthreads();
    float m2 = 0.f;
    if (active) {
#pragma unroll
        for (int k = 0; k < 8; k++) m2 += sDi[ln][i * 8 + k] * sA[ln][k * 8 + j];
    }
    __syncthreads();
    if (active) sA[ln][el] = m2;
    __syncthreads();
    if (active) {
        float m3 = 0.f;
#pragma unroll
        for (int k = 0; k < 8; k++) m3 += sA[ln][i * 8 + k] * sDj[ln][k * 8 + j];
        g_eb[p * DD + el] = m3;
    }
}

// K5: megawrite — single streaming pass producing the full 256MB output:
// zeros, compact edge blocks, and diagonal blocks, fully coalesced STG.128.
// CTA = 256 threads handles an 8-row x 512-col strip (16KB).
// Table entries validated against E (L2-resident, 256KB).
__global__ void k_write(float4* __restrict__ out4, const int* __restrict__ E, int P) {
    int bi = blockIdx.x >> 4;       // block-row
    int s = blockIdx.x & 15;        // strip within row
    int cb0 = s << 6;               // first col-block of strip
    __shared__ int sp[64];
    int t = threadIdx.x;
    if (t < 64) {
        int bj = cb0 + t;
        int p;
        if (bj == bi) {
            p = 0x40000000 | bi;
        } else {
            p = __ldg(&g_tab[bi * NNODE + bj]);
            if (p < 0 || p >= P || __ldg(&E[2 * p]) != bi || __ldg(&E[2 * p + 1]) != bj)
                p = -1;
        }
        sp[t] = p;
    }
    __syncthreads();
    const float4* ebv = (const float4*)g_eb;
    const float4* dbv = (const float4*)g_db;
    float4 z = make_float4(0.f, 0.f, 0.f, 0.f);
#pragma unroll
    for (int k = 0; k < 4; k++) {
        int f = t + (k << 8);       // 0..1023
        int row = f >> 7;           // 0..7
        int c4 = f & 127;           // float4 col within strip
        int blk = c4 >> 1;
        int half = c4 & 1;
        int p = sp[blk];
        float4 v = z;
        if (p >= 0) {
            if (p & 0x40000000) v = dbv[(p & 0x3FF) * 16 + row * 2 + half];
            else                v = ebv[p * 16 + row * 2 + half];
        }
        out4[(long)(bi * 8 + row) * (OUTDIM / 4) + (s << 7) + c4] = v;
    }
}

// ---------------------------------------------------------------------------
extern "C" void kernel_launch(void* const* d_in, const int* in_sizes, int n_in,
                              void* d_out, int out_size) {
    const float* R = (const float*)d_in[0];
    const int* E = (const int*)d_in[1];
    const float* L1 = nullptr;
    for (int k = 2; k < n_in; k++) {
        if (in_sizes[k] == NNODE * NNODE) { L1 = (const float*)d_in[k]; break; }
    }
    if (!L1) L1 = (const float*)d_in[n_in - 1];

    float* out = (float*)d_out;
    int P = in_sizes[1] / 2;
    if (P > PMAX) P = PMAX;

    k_scatter<<<(P + 255) / 256, 256>>>(E, P);
    k_ftf<<<(P + 15) / 16, 256>>>(R, E, P);
    k_node<<<NNODE / 8, 256>>>();
    k_edge<<<(P + 3) / 4, 256>>>(R, E, L1, P);
    k_write<<<NNODE * 16, 256>>>((float4*)out, E, P);
}

// round 12
// speedup vs baseline: 1.1183x; 1.1183x over previous
#include <cuda_runtime.h>
#include <cuda_bf16.h>
#include <stdint.h>

#define NNODE 1024
#define SD 8
#define DD 64
#define OUTDIM 8192
#define EPSV 1e-4f
#define NS_ITERS 18
#define PMAX 32768

// Static device scratch. g_tab is validated-on-read (never initialized):
// entry p valid iff 0<=p<P && E[2p]==i && E[2p+1]==j. g_diag is zero-init at
// module load and re-zeroed by k_node after consumption -> every replay sees 0.
__device__ float g_diag[NNODE * DD];
__device__ float g_dis[NNODE * DD];
__device__ float g_db[NNODE * DD];
__device__ float g_h[PMAX * DD];          // H_p = R_p * Dis_dst(p)
__device__ float g_eb[PMAX * DD];         // off-diagonal blocks
__device__ int   g_tab[NNODE * NNODE];

// ---------------------------------------------------------------------------
// K1: FtF[p]=R_p^T R_p atomically into g_diag[src]; also scatter table.
// 16 edges/CTA, burst float4 shared load.
__global__ void k_ftf(const float* __restrict__ R, const int* __restrict__ E, int P) {
    __shared__ float sR[16 * DD];
    __shared__ int ssrc[16];
    int t = threadIdx.x;
    int e0 = blockIdx.x * 16;
    int nE = P - e0; if (nE > 16) nE = 16;
    const float4* Rv = (const float4*)(R + (long)e0 * DD);
    if (t < nE * 16) ((float4*)sR)[t] = Rv[t];
    if (t < nE) {
        int i = __ldg(&E[2 * (e0 + t)]);
        int j = __ldg(&E[2 * (e0 + t) + 1]);
        ssrc[t] = i;
        g_tab[i * NNODE + j] = e0 + t;
    }
    __syncthreads();
    int grp = t >> 6, el = t & 63;
    int i = el >> 3, j = el & 7;
#pragma unroll
    for (int q = 0; q < 4; q++) {
        int le = grp * 4 + q;
        if (le < nE) {
            const float* r = &sR[le * DD];
            float v = 0.f;
#pragma unroll
            for (int k = 0; k < 8; k++) v += r[k * 8 + i] * r[k * 8 + j];
            atomicAdd(&g_diag[ssrc[le] * DD + el], v);
        }
    }
}

// ---------------------------------------------------------------------------
// K2: warp-per-node Newton-Schulz D^{-1/2}; writes g_dis and diagonal block
// g_db = Dis*diag_raw*Dis; re-zeroes g_diag for the next replay.
__global__ void k_node() {
    __shared__ float sD[8][DD], sY[8][DD], sZ[8][DD], sT[8][DD];
    int t = threadIdx.x;
    int w = t >> 5, lane = t & 31;
    int node = blockIdx.x * 8 + w;
    int e0 = lane, e1 = lane + 32;
    int i0 = e0 >> 3, j0 = e0 & 7, i1 = e1 >> 3, j1 = e1 & 7;

    sD[w][e0] = g_diag[node * DD + e0];
    sD[w][e1] = g_diag[node * DD + e1];
    g_diag[node * DD + e0] = 0.f;      // reset accumulator for next replay
    g_diag[node * DD + e1] = 0.f;
    __syncwarp();

    float c = 8.f * EPSV;
#pragma unroll
    for (int k = 0; k < 8; k++) c += sD[w][k * 9];
    float invc = 1.f / c;

    float y0 = (0.5f * (sD[w][e0] + sD[w][j0 * 8 + i0]) + ((i0 == j0) ? EPSV : 0.f)) * invc;
    float y1 = (0.5f * (sD[w][e1] + sD[w][j1 * 8 + i1]) + ((i1 == j1) ? EPSV : 0.f)) * invc;
    __syncwarp();
    sY[w][e0] = y0; sY[w][e1] = y1;
    sZ[w][e0] = (i0 == j0) ? 1.f : 0.f;
    sZ[w][e1] = (i1 == j1) ? 1.f : 0.f;
    __syncwarp();

    for (int it = 0; it < NS_ITERS; it++) {
        float t0 = 0.f, t1 = 0.f;
#pragma unroll
        for (int k = 0; k < 8; k++) {
            t0 += sZ[w][i0 * 8 + k] * sY[w][k * 8 + j0];
            t1 += sZ[w][i1 * 8 + k] * sY[w][k * 8 + j1];
        }
        __syncwarp();
        sT[w][e0] = t0; sT[w][e1] = t1;
        __syncwarp();
        float ny0 = 0.f, ny1 = 0.f, nz0 = 0.f, nz1 = 0.f;
#pragma unroll
        for (int k = 0; k < 8; k++) {
            ny0 += sY[w][i0 * 8 + k] * sT[w][k * 8 + j0];
            ny1 += sY[w][i1 * 8 + k] * sT[w][k * 8 + j1];
            nz0 += sT[w][i0 * 8 + k] * sZ[w][k * 8 + j0];
            nz1 += sT[w][i1 * 8 + k] * sZ[w][k * 8 + j1];
        }
        ny0 = 1.5f * sY[w][e0] - 0.5f * ny0;
        ny1 = 1.5f * sY[w][e1] - 0.5f * ny1;
        nz0 = 1.5f * sZ[w][e0] - 0.5f * nz0;
        nz1 = 1.5f * sZ[w][e1] - 0.5f * nz1;
        __syncwarp();
        sY[w][e0] = ny0; sY[w][e1] = ny1;
        sZ[w][e0] = nz0; sZ[w][e1] = nz1;
        __syncwarp();
    }

    float rs = rsqrtf(c);
    float d0 = sZ[w][e0] * rs, d1 = sZ[w][e1] * rs;
    __syncwarp();
    sT[w][e0] = d0; sT[w][e1] = d1;
    __syncwarp();
    d0 = 0.5f * (sT[w][e0] + sT[w][j0 * 8 + i0]);
    d1 = 0.5f * (sT[w][e1] + sT[w][j1 * 8 + i1]);
    g_dis[node * DD + e0] = d0;
    g_dis[node * DD + e1] = d1;
    __syncwarp();
    sZ[w][e0] = d0; sZ[w][e1] = d1;
    __syncwarp();
    float b0 = 0.f, b1 = 0.f;
#pragma unroll
    for (int k = 0; k < 8; k++) {
        b0 += sZ[w][i0 * 8 + k] * sD[w][k * 8 + j0];
        b1 += sZ[w][i1 * 8 + k] * sD[w][k * 8 + j1];
    }
    __syncwarp();
    sT[w][e0] = b0; sT[w][e1] = b1;
    __syncwarp();
    float c0 = 0.f, c1 = 0.f;
#pragma unroll
    for (int k = 0; k < 8; k++) {
        c0 += sT[w][i0 * 8 + k] * sZ[w][k * 8 + j0];
        c1 += sT[w][i1 * 8 + k] * sZ[w][k * 8 + j1];
    }
    g_db[node * DD + e0] = c0;
    g_db[node * DD + e1] = c1;
}

// ---------------------------------------------------------------------------
// K3: H_p = R_p * Dis_dst(p). 16 edges/CTA; 16 threads per edge, each
// computes one float4 segment of a row. Only 2 barriers.
__global__ void k_h(const float* __restrict__ R, const int* __restrict__ E, int P) {
    __shared__ float sR[16 * DD];
    __shared__ float sDs[16 * DD];
    __shared__ int sdst[16];
    int t = threadIdx.x;
    int e0 = blockIdx.x * 16;
    int nE = P - e0; if (nE > 16) nE = 16;
    const float4* Rv = (const float4*)(R + (long)e0 * DD);
    if (t < nE * 16) ((float4*)sR)[t] = Rv[t];
    if (t < nE) sdst[t] = __ldg(&E[2 * (e0 + t) + 1]);
    __syncthreads();
    int le = t >> 4, q = t & 15;
    if (le < nE) ((float4*)sDs)[t] = ((const float4*)g_dis)[sdst[le] * 16 + q];
    __syncthreads();
    if (le < nE) {
        int i = q >> 1, cg = (q & 1) * 4;
        const float* r = &sR[le * DD + i * 8];
        const float* dsc = &sDs[le * DD];
        float c0 = 0.f, c1 = 0.f, c2 = 0.f, c3 = 0.f;
#pragma unroll
        for (int k = 0; k < 8; k++) {
            float a = r[k];
            c0 += a * dsc[k * 8 + cg + 0];
            c1 += a * dsc[k * 8 + cg + 1];
            c2 += a * dsc[k * 8 + cg + 2];
            c3 += a * dsc[k * 8 + cg + 3];
        }
        ((float4*)g_h)[(e0 + le) * 16 + q] = make_float4(c0, c1, c2, c3);
    }
}

// ---------------------------------------------------------------------------
// K4: g_eb[p] = -sign(L1[i,j]) * H_rev^T * H_p (0 if reverse edge missing).
// 16 edges/CTA; per-edge lookup done by 16 parallel threads.
__global__ void k_blk(const int* __restrict__ E, const float* __restrict__ L1, int P) {
    __shared__ float sHp[16 * DD];
    __shared__ float sHr[16 * DD];
    __shared__ int srev[16];
    __shared__ float ssgn[16];
    int t = threadIdx.x;
    int e0 = blockIdx.x * 16;
    int nE = P - e0; if (nE > 16) nE = 16;
    if (t < nE * 16) ((float4*)sHp)[t] = ((const float4*)g_h)[e0 * 16 + t];
    if (t < nE) {
        int p = e0 + t;
        int i = __ldg(&E[2 * p]);
        int j = __ldg(&E[2 * p + 1]);
        int rev = g_tab[j * NNODE + i];
        if (rev < 0 || rev >= P || __ldg(&E[2 * rev]) != j || __ldg(&E[2 * rev + 1]) != i)
            rev = -1;
        srev[t] = rev;
        float x = __ldg(&L1[(long)i * NNODE + j]);
        ssgn[t] = (x > 0.f) ? -1.f : ((x < 0.f) ? 1.f : 0.f);
    }
    __syncthreads();
    int le = t >> 4, q = t & 15;
    if (le < nE) {
        int rv = srev[le];
        float4 z = make_float4(0.f, 0.f, 0.f, 0.f);
        ((float4*)sHr)[t] = (rv >= 0) ? ((const float4*)g_h)[rv * 16 + q] : z;
    }
    __syncthreads();
    if (le < nE) {
        int i = q >> 1, cg = (q & 1) * 4;
        float s = ssgn[le];
        const float* hr = &sHr[le * DD];
        const float* hp = &sHp[le * DD];
        float c0 = 0.f, c1 = 0.f, c2 = 0.f, c3 = 0.f;
#pragma unroll
        for (int k = 0; k < 8; k++) {
            float a = hr[k * 8 + i];
            c0 += a * hp[k * 8 + cg + 0];
            c1 += a * hp[k * 8 + cg + 1];
            c2 += a * hp[k * 8 + cg + 2];
            c3 += a * hp[k * 8 + cg + 3];
        }
        ((float4*)g_eb)[(e0 + le) * 16 + q] = make_float4(s * c0, s * c1, s * c2, s * c3);
    }
}

// ---------------------------------------------------------------------------
// K5: megawrite — single streaming pass producing the full 256MB output.
// CTA = 8-row x 512-col strip; table entries validated against E.
__global__ void k_write(float4* __restrict__ out4, const int* __restrict__ E, int P) {
    int bi = blockIdx.x >> 4;
    int s = blockIdx.x & 15;
    int cb0 = s << 6;
    __shared__ int sp[64];
    int t = threadIdx.x;
    if (t < 64) {
        int bj = cb0 + t;
        int p;
        if (bj == bi) {
            p = 0x40000000 | bi;
        } else {
            p = __ldg(&g_tab[bi * NNODE + bj]);
            if (p < 0 || p >= P || __ldg(&E[2 * p]) != bi || __ldg(&E[2 * p + 1]) != bj)
                p = -1;
        }
        sp[t] = p;
    }
    __syncthreads();
    const float4* ebv = (const float4*)g_eb;
    const float4* dbv = (const float4*)g_db;
    float4 z = make_float4(0.f, 0.f, 0.f, 0.f);
#pragma unroll
    for (int k = 0; k < 4; k++) {
        int f = t + (k << 8);
        int row = f >> 7;
        int c4 = f & 127;
        int blk = c4 >> 1;
        int half = c4 & 1;
        int p = sp[blk];
        float4 v = z;
        if (p >= 0) {
            if (p & 0x40000000) v = dbv[(p & 0x3FF) * 16 + row * 2 + half];
            else                v = ebv[p * 16 + row * 2 + half];
        }
        out4[(long)(bi * 8 + row) * (OUTDIM / 4) + (s << 7) + c4] = v;
    }
}

// ---------------------------------------------------------------------------
extern "C" void kernel_launch(void* const* d_in, const int* in_sizes, int n_in,
                              void* d_out, int out_size) {
    const float* R = (const float*)d_in[0];
    const int* E = (const int*)d_in[1];
    const float* L1 = nullptr;
    for (int k = 2; k < n_in; k++) {
        if (in_sizes[k] == NNODE * NNODE) { L1 = (const float*)d_in[k]; break; }
    }
    if (!L1) L1 = (const float*)d_in[n_in - 1];

    float* out = (float*)d_out;
    int P = in_sizes[1] / 2;
    if (P > PMAX) P = PMAX;

    int gE = (P + 15) / 16;
    k_ftf<<<gE, 256>>>(R, E, P);
    k_node<<<NNODE / 8, 256>>>();
    k_h<<<gE, 256>>>(R, E, P);
    k_blk<<<gE, 256>>>(E, L1, P);
    k_write<<<NNODE * 16, 256>>>((float4*)out, E, P);
}